// round 7
// baseline (speedup 1.0000x reference)
#include <cuda_runtime.h>
#include <math_constants.h>

// SpatialAttention: out = x * hardsigmoid(conv3x3([mean_c(x); max_c(x)]))
// x: [16, 256, 128, 128] fp32, conv_w: [1, 2, 3, 3] fp32.
//
// SINGLE-LAUNCH pipelined kernel. Block groups (bid-ordered):
//   group g: reduce(chunk g) | conv(chunk g-1) | mul(chunk g-2)
// Cross-phase deps enforced with device counters + spin (producers always
// have lower bids than their consumers -> dispatch order guarantees
// progress). Counters are reset by the last consumer, so every graph
// replay starts from a clean state.

#define BATCH 16
#define CH    256
#define HH    128
#define WW    128
#define HWSZ  (HH * WW)          // 16384
#define HW4   (HWSZ / 4)         // 4096 float4 cols per (b,c) plane
#define NCHNK 16                 // 1 batch per chunk (16 MiB x-slice)

#define COLS_PER_BLK 16
#define NGRP  16                 // channel groups per reduce block
#define CPS   (CH / NGRP)        // 16 channels per group

#define R_BLK 256                // reduce blocks per chunk (HW4/16)
#define C_BLK 64                 // conv blocks per chunk (HWSZ/256)
#define M_BLK 4096               // mul blocks per chunk (CH*HW4/256)
#define GRP_BLK (R_BLK + C_BLK + M_BLK)   // 4416
#define NGROUPS (NCHNK + 2)               // 18 (incl. fill/drain)

__device__ float g_avg[BATCH * HWSZ];
__device__ float g_max[BATCH * HWSZ];
__device__ float g_att[BATCH * HWSZ];

// dependency counters (zero-init; reset by last consumer each run)
__device__ int g_cnt_r[NCHNK];   // reduce(j) blocks done
__device__ int g_cnt_c[NCHNK];   // conv(j)   blocks done
__device__ int g_pass_r[NCHNK];  // conv(j) blocks past their wait
__device__ int g_pass_c[NCHNK];  // mul(j)  blocks past their wait

__device__ __forceinline__ void spin_wait(volatile int* p, int target) {
    if (threadIdx.x == 0) {
        while (*p < target) __nanosleep(256);
        __threadfence();                 // acquire: make producer data visible
    }
    __syncthreads();
}

__global__ void __launch_bounds__(256, 6)
fused_kernel(const float* __restrict__ x, const float* __restrict__ wt,
             float* __restrict__ out) {
    __shared__ float4 ssum[256];
    __shared__ float4 smax[256];

    int g = blockIdx.x / GRP_BLK;        // pipeline group 0..17
    int r = blockIdx.x % GRP_BLK;
    int t = threadIdx.x;

    if (r < R_BLK) {
        // ---------------- reduce phase: chunk g ----------------
        if (g >= NCHNK) return;
        int b       = g;
        int colBase = r * COLS_PER_BLK;
        int col_l   = t & (COLS_PER_BLK - 1);
        int cg      = t >> 4;            // 0..15 channel group

        const float4* xp = reinterpret_cast<const float4*>(x)
                         + (size_t)b * CH * HW4 + (size_t)cg * CPS * HW4
                         + colBase + col_l;

        float4 s = make_float4(0.f, 0.f, 0.f, 0.f);
        float4 m = make_float4(-CUDART_INF_F, -CUDART_INF_F, -CUDART_INF_F, -CUDART_INF_F);

        #pragma unroll 8
        for (int c = 0; c < CPS; c++) {
            float4 v = xp[c * HW4];
            s.x += v.x; s.y += v.y; s.z += v.z; s.w += v.w;
            m.x = fmaxf(m.x, v.x); m.y = fmaxf(m.y, v.y);
            m.z = fmaxf(m.z, v.z); m.w = fmaxf(m.w, v.w);
        }
        ssum[t] = s; smax[t] = m;
        __syncthreads();

        #pragma unroll
        for (int off = 128; off >= COLS_PER_BLK; off >>= 1) {
            if (t < off) {
                float4 s2 = ssum[t + off], m2 = smax[t + off];
                float4 sa = ssum[t],       ma = smax[t];
                sa.x += s2.x; sa.y += s2.y; sa.z += s2.z; sa.w += s2.w;
                ma.x = fmaxf(ma.x, m2.x); ma.y = fmaxf(ma.y, m2.y);
                ma.z = fmaxf(ma.z, m2.z); ma.w = fmaxf(ma.w, m2.w);
                ssum[t] = sa; smax[t] = ma;
            }
            __syncthreads();
        }

        if (t < COLS_PER_BLK) {
            const float inv = 1.0f / (float)CH;
            float4 sa = ssum[t], ma = smax[t];
            float4 a = make_float4(sa.x * inv, sa.y * inv, sa.z * inv, sa.w * inv);
            reinterpret_cast<float4*>(g_avg)[b * HW4 + colBase + t] = a;
            reinterpret_cast<float4*>(g_max)[b * HW4 + colBase + t] = ma;
        }
        __syncthreads();
        if (t == 0) {                    // release: publish avg/max, signal
            __threadfence();
            atomicAdd(&g_cnt_r[b], 1);
        }
    } else if (r < R_BLK + C_BLK) {
        // ---------------- conv phase: chunk g-1 ----------------
        int b = g - 1;
        if (b < 0 || b >= NCHNK) return;

        spin_wait(&g_cnt_r[b], R_BLK);
        if (t == 0) {                    // reset reduce counter (last of 64)
            int old = atomicAdd(&g_pass_r[b], 1);
            if (old == C_BLK - 1) { g_cnt_r[b] = 0; g_pass_r[b] = 0; }
        }

        int idx = (r - R_BLK) * 256 + t; // 0 .. HWSZ-1
        int h   = idx >> 7;
        int w   = idx & (WW - 1);

        const float* __restrict__ A = g_avg + b * HWSZ;
        const float* __restrict__ M = g_max + b * HWSZ;

        float acc = 0.f;
        #pragma unroll
        for (int kh = 0; kh < 3; kh++) {
            int hh = h + kh - 1;
            if (hh < 0 || hh >= HH) continue;
            #pragma unroll
            for (int kw = 0; kw < 3; kw++) {
                int ww = w + kw - 1;
                if (ww < 0 || ww >= WW) continue;
                int o = hh * WW + ww;
                acc += __ldg(&wt[kh * 3 + kw])     * A[o]
                     + __ldg(&wt[9 + kh * 3 + kw]) * M[o];
            }
        }
        float y = fminf(fmaxf(acc + 3.0f, 0.0f), 6.0f) * (1.0f / 6.0f);
        g_att[b * HWSZ + idx] = y;

        __syncthreads();
        if (t == 0) {                    // release: publish att, signal
            __threadfence();
            atomicAdd(&g_cnt_c[b], 1);
        }
    } else {
        // ---------------- mul phase: chunk g-2 ----------------
        int b = g - 2;
        if (b < 0 || b >= NCHNK) return;

        spin_wait(&g_cnt_c[b], C_BLK);
        if (t == 0) {                    // reset conv counter (last of 4096)
            int old = atomicAdd(&g_pass_c[b], 1);
            if (old == M_BLK - 1) { g_cnt_c[b] = 0; g_pass_c[b] = 0; }
        }

        int idx = (r - R_BLK - C_BLK) * 256 + t;   // 0 .. CH*HW4-1
        int col = idx & (HW4 - 1);

        size_t gidx = (size_t)b * CH * HW4 + idx;

        float4 v = __ldcs(reinterpret_cast<const float4*>(x) + gidx);
        float4 a = __ldg(reinterpret_cast<const float4*>(g_att) + (size_t)b * HW4 + col);

        v.x *= a.x; v.y *= a.y; v.z *= a.z; v.w *= a.w;
        __stcs(reinterpret_cast<float4*>(out) + gidx, v);
    }
}

extern "C" void kernel_launch(void* const* d_in, const int* in_sizes, int n_in,
                              void* d_out, int out_size) {
    const float* x  = (const float*)d_in[0];
    const float* wt = (const float*)d_in[1];
    float* out      = (float*)d_out;

    fused_kernel<<<NGROUPS * GRP_BLK, 256>>>(x, wt, out);   // one launch
}